// round 2
// baseline (speedup 1.0000x reference)
#include <cuda_runtime.h>

// CrossConv2d: out[b,s,:,h,w] = relu( BN(conv3x3(concat(u[b], v[b,s]))) + concat(u[b], v[b,s]) )
// Shapes: u (4,1,64,128,128), v (4,8,64,128,128), w (128,128,3,3) OIHW,
//         bn_* (128,), out (4,1,8,128,128,128) fp32.
//
// Strategy (round 1): SIMT direct conv, FMA-pipe bound, using sm_103a packed
// fma.rn.f32x2 to double fp32 FMA throughput. Tile per block (256 thr):
//   64 out-channels x 4 rows x 32 cols; ci chunked by 8.
// Accumulators: channel-pairs packed in b64 (16 pairs = 32 outputs/thread).
// Weights staged in smem with XOR swizzle (co ^ (rk&30)) -> conflict-light
// stores AND aligned LDS.64 channel-pair loads. Input patch staged 8x6x36.

#define EPSV 1e-5f

constexpr int Bn = 4, Sn = 8, C1n = 64, CCn = 128, Hn = 128, Wn = 128;
constexpr int CO_T = 64, H_T = 4, W_T = 32, CI_T = 8;

__device__ __forceinline__ unsigned long long pack2(float lo, float hi) {
    unsigned long long r;
    asm("mov.b64 %0, {%1, %2};" : "=l"(r) : "f"(lo), "f"(hi));
    return r;
}
__device__ __forceinline__ void unpack2(unsigned long long p, float& lo, float& hi) {
    asm("mov.b64 {%0, %1}, %2;" : "=f"(lo), "=f"(hi) : "l"(p));
}
__device__ __forceinline__ void ffma2(unsigned long long& d, unsigned long long a,
                                      unsigned long long b) {
    // packed dual fp32 FMA (sm_100+); d.lo += a.lo*b.lo, d.hi += a.hi*b.hi
    asm("fma.rn.f32x2 %0, %1, %2, %0;" : "+l"(d) : "l"(a), "l"(b));
}

__global__ __launch_bounds__(256)
void cross_conv_kernel(const float* __restrict__ u, const float* __restrict__ v,
                       const float* __restrict__ w, const float* __restrict__ gma,
                       const float* __restrict__ bta, const float* __restrict__ mean,
                       const float* __restrict__ var, float* __restrict__ out) {
    __shared__ float s_in[CI_T][H_T + 2][W_T + 4];          // [8][6][36]
    __shared__ __align__(16) float s_w[CI_T * 9 * CO_T];    // swizzled [rk][co]

    const int tid = threadIdx.x;
    const int tx = tid & 31;          // w within tile
    const int ty = tid >> 5;          // 8 groups of 8 output channels
    const int img = blockIdx.z;       // b*8 + s
    const int b = img >> 3, s = img & 7;
    const int h0 = blockIdx.y * H_T;
    const int w0 = (blockIdx.x >> 1) * W_T;
    const int co0 = (blockIdx.x & 1) * CO_T;

    unsigned long long acc[4][4];     // [co-pair j2][row hh]
#pragma unroll
    for (int a = 0; a < 4; a++)
#pragma unroll
        for (int c = 0; c < 4; c++) acc[a][c] = 0ull;

    const float* ubase = u + (size_t)b * C1n * Hn * Wn;
    const float* vbase = v + (size_t)(b * Sn + s) * C1n * Hn * Wn;

    for (int ci0 = 0; ci0 < CCn; ci0 += CI_T) {
        __syncthreads();  // previous chunk fully consumed before overwrite

        // --- stage input patch: 8 ci x 6 rows x 34 cols (zero-padded halo) ---
        for (int idx = tid; idx < CI_T * (H_T + 2) * 34; idx += 256) {
            int c = idx % 34;
            int r = (idx / 34) % (H_T + 2);
            int ci = idx / (34 * (H_T + 2));
            int gh = h0 - 1 + r, gw = w0 - 1 + c;
            float val = 0.f;
            if ((unsigned)gh < (unsigned)Hn && (unsigned)gw < (unsigned)Wn) {
                int cig = ci0 + ci;
                val = (cig < C1n)
                          ? ubase[((size_t)cig * Hn + gh) * Wn + gw]
                          : vbase[((size_t)(cig - C1n) * Hn + gh) * Wn + gw];
            }
            s_in[ci][r][c] = val;
        }

        // --- stage weights: coalesced global read, XOR-swizzled smem store ---
        // smem addr = rk*64 + (co ^ (rk & 30)); keeps even/odd co pairs adjacent
        for (int idx = tid; idx < CO_T * CI_T * 9; idx += 256) {
            int rk = idx % 72;  // ci*9 + k
            int co = idx / 72;
            float wv = w[((size_t)(co0 + co) * CCn + ci0) * 9 + rk];
            s_w[rk * 64 + (co ^ (rk & 30))] = wv;
        }
        __syncthreads();

        // --- compute: 8 ci x 3x3 taps, 16 packed FMA per tap ---
#pragma unroll 2
        for (int ci = 0; ci < CI_T; ci++) {
#pragma unroll
            for (int kw = 0; kw < 3; kw++) {
                unsigned long long p[6];
#pragma unroll
                for (int r = 0; r < 6; r++) {
                    float x = s_in[ci][r][tx + kw];
                    p[r] = pack2(x, x);  // splat
                }
#pragma unroll
                for (int kh = 0; kh < 3; kh++) {
                    int rk = ci * 9 + kh * 3 + kw;
                    const float* wb = &s_w[rk * 64];
                    int m = rk & 30;
                    unsigned long long wp[4];
#pragma unroll
                    for (int j2 = 0; j2 < 4; j2++)
                        wp[j2] = *reinterpret_cast<const unsigned long long*>(
                            &wb[(ty * 8 + 2 * j2) ^ m]);
#pragma unroll
                    for (int j2 = 0; j2 < 4; j2++)
#pragma unroll
                        for (int hh = 0; hh < 4; hh++)
                            ffma2(acc[j2][hh], wp[j2], p[kh + hh]);
                }
            }
        }
    }

    // --- epilogue: BN affine + identity skip + ReLU ---
    const int gw = w0 + tx;
    float sc[8], sh[8];
#pragma unroll
    for (int j = 0; j < 8; j++) {
        int co = co0 + ty * 8 + j;
        float scv = gma[co] * rsqrtf(var[co] + EPSV);
        sc[j] = scv;
        sh[j] = bta[co] - mean[co] * scv;
    }
    float* obase = out + (size_t)(b * Sn + s) * CCn * Hn * Wn;
#pragma unroll
    for (int hh = 0; hh < H_T; hh++) {
        int gh = h0 + hh;
#pragma unroll
        for (int j2 = 0; j2 < 4; j2++) {
            float pv[2];
            unpack2(acc[j2][hh], pv[0], pv[1]);
#pragma unroll
            for (int t = 0; t < 2; t++) {
                int j = 2 * j2 + t;
                int co = co0 + ty * 8 + j;
                float skip = (co < C1n)
                                 ? ubase[((size_t)co * Hn + gh) * Wn + gw]
                                 : vbase[((size_t)(co - C1n) * Hn + gh) * Wn + gw];
                float y = pv[t] * sc[j] + sh[j] + skip;
                obase[((size_t)co * Hn + gh) * Wn + gw] = fmaxf(y, 0.f);
            }
        }
    }
}

extern "C" void kernel_launch(void* const* d_in, const int* in_sizes, int n_in,
                              void* d_out, int out_size) {
    const float* u = (const float*)d_in[0];
    const float* v = (const float*)d_in[1];
    const float* w = (const float*)d_in[2];
    const float* g = (const float*)d_in[3];
    const float* bt = (const float*)d_in[4];
    const float* mn = (const float*)d_in[5];
    const float* vr = (const float*)d_in[6];

    dim3 grid(8, 32, 32);  // (w_tiles*co_tiles, h_tiles, images)
    cross_conv_kernel<<<grid, 256>>>(u, v, w, g, bt, mn, vr, (float*)d_out);
}

// round 3
// speedup vs baseline: 1.3411x; 1.3411x over previous
#include <cuda_runtime.h>

// CrossConv2d fused: relu( BN(conv3x3(concat(u,v))) + concat(u,v) )
// u (4,1,64,128,128), v (4,8,64,128,128), w (128,128,3,3) OIHW, out fp32.
//
// Round 3: pure-FMA inner loop.
//  - Fully unrolled ci chunk -> all LDS offsets are compile-time immediates.
//  - Weight smem layout [rk][co] with stride 66 (even, padded): staging
//    stores <=2-way conflict; compute loads are warp-uniform broadcasts.
//  - Input patch stored as duplicated float2 -> LDS.64 yields the f32x2
//    splat directly (no MOV pairs).
//  - Division-free staging: warp w stages input channel w; weight rows
//    per (warp, j) with lane = rk.

#define EPSV 1e-5f

constexpr int C1n = 64, CCn = 128, Hn = 128, Wn = 128, HW = Hn * Wn;
constexpr int CO_T = 64, H_T = 4, W_T = 32, CI_T = 8;

typedef unsigned long long u64;

__device__ __forceinline__ void ffma2(u64& d, u64 a, u64 b) {
    asm("fma.rn.f32x2 %0, %1, %2, %0;" : "+l"(d) : "l"(a), "l"(b));
}
__device__ __forceinline__ void unpack2(u64 p, float& lo, float& hi) {
    asm("mov.b64 {%0, %1}, %2;" : "=f"(lo), "=f"(hi) : "l"(p));
}

__global__ __launch_bounds__(256, 2)
void cross_conv_kernel(const float* __restrict__ u, const float* __restrict__ v,
                       const float* __restrict__ w, const float* __restrict__ gma,
                       const float* __restrict__ bta, const float* __restrict__ mean,
                       const float* __restrict__ var, float* __restrict__ out) {
    __shared__ __align__(16) float2 s_in[CI_T][H_T + 2][36];   // duplicated pairs
    __shared__ __align__(16) float s_w[72 * 66 + 8];           // [rk]*66 + [co]

    const int tid = threadIdx.x;
    const int lane = tid & 31;        // w within tile
    const int warp = tid >> 5;        // 8 warps: co-group in compute, ci in staging
    const int img = blockIdx.z;
    const int b = img >> 3, s = img & 7;
    const int h0 = blockIdx.y * H_T;
    const int w0 = (blockIdx.x >> 1) * W_T;
    const int co0 = (blockIdx.x & 1) * CO_T;

    const float* ubase = u + (size_t)b * C1n * HW;
    const float* vbase = v + (size_t)(b * 8 + s) * C1n * HW;

    u64 acc[4][H_T];   // [co-pair][row]
#pragma unroll
    for (int a = 0; a < 4; a++)
#pragma unroll
        for (int c = 0; c < H_T; c++) acc[a][c] = 0ull;

    for (int ci0 = 0; ci0 < CCn; ci0 += CI_T) {
        __syncthreads();

        // ---- stage input: warp stages its own channel plane (6 x 34 halo) ----
        {
            const float* base = (ci0 < C1n) ? ubase + (size_t)ci0 * HW
                                            : vbase + (size_t)(ci0 - C1n) * HW;
            const float* sp = base + (size_t)warp * HW;
            const int gw1 = w0 - 1 + lane;
            const bool w1ok = (unsigned)gw1 < (unsigned)Wn;
#pragma unroll
            for (int r = 0; r < H_T + 2; r++) {
                int gh = h0 - 1 + r;
                bool hok = (unsigned)gh < (unsigned)Hn;
                float v1 = 0.f;
                if (hok && w1ok) v1 = sp[gh * Wn + gw1];
                s_in[warp][r][lane] = make_float2(v1, v1);
                if (lane < 2) {
                    int gw2 = gw1 + 32;
                    float v2 = 0.f;
                    if (hok && (unsigned)gw2 < (unsigned)Wn) v2 = sp[gh * Wn + gw2];
                    s_in[warp][r][lane + 32] = make_float2(v2, v2);
                }
            }
        }

        // ---- stage weights: warp handles 8 consecutive co, lane = rk ----
#pragma unroll
        for (int j = 0; j < 8; j++) {
            int co = warp * 8 + j;
            const float* wr = w + (size_t)(co0 + co) * (CCn * 9) + ci0 * 9;
            s_w[lane * 66 + co] = wr[lane];
            s_w[(lane + 32) * 66 + co] = wr[lane + 32];
            if (lane < 8) s_w[(lane + 64) * 66 + co] = wr[lane + 64];
        }
        __syncthreads();

        // ---- compute: everything compile-time indexed ----
#pragma unroll
        for (int ci = 0; ci < CI_T; ci++) {
#pragma unroll
            for (int kw = 0; kw < 3; kw++) {
                u64 p[H_T + 2];
#pragma unroll
                for (int r = 0; r < H_T + 2; r++)
                    p[r] = *reinterpret_cast<const u64*>(&s_in[ci][r][lane + kw]);
#pragma unroll
                for (int kh = 0; kh < 3; kh++) {
                    const int rk = ci * 9 + kh * 3 + kw;
                    u64 wp[4];
#pragma unroll
                    for (int j2 = 0; j2 < 4; j2++)
                        wp[j2] = *reinterpret_cast<const u64*>(
                            &s_w[rk * 66 + warp * 8 + 2 * j2]);
#pragma unroll
                    for (int j2 = 0; j2 < 4; j2++)
#pragma unroll
                        for (int hh = 0; hh < H_T; hh++)
                            ffma2(acc[j2][hh], wp[j2], p[kh + hh]);
                }
            }
        }
    }

    // ---- epilogue: BN affine + identity skip + ReLU ----
    const int gw = w0 + lane;
    float sc[8], sh[8];
#pragma unroll
    for (int j = 0; j < 8; j++) {
        int co = co0 + warp * 8 + j;
        float scv = gma[co] * rsqrtf(var[co] + EPSV);
        sc[j] = scv;
        sh[j] = bta[co] - mean[co] * scv;
    }
    // all 8 co of this thread live entirely in u-half or v-half (co0 picks it)
    const float* skipb = co0 ? vbase : ubase;
    float* obase = out + (size_t)(b * 8 + s) * CCn * HW;
#pragma unroll
    for (int hh = 0; hh < H_T; hh++) {
        int gh = h0 + hh;
#pragma unroll
        for (int j2 = 0; j2 < 4; j2++) {
            float pv0, pv1;
            unpack2(acc[j2][hh], pv0, pv1);
            float pv[2] = {pv0, pv1};
#pragma unroll
            for (int t = 0; t < 2; t++) {
                int j = 2 * j2 + t;
                int coloc = warp * 8 + j;                      // 0..63
                float skip = skipb[(size_t)coloc * HW + gh * Wn + gw];
                float y = pv[t] * sc[j] + sh[j] + skip;
                out[(size_t)(b * 8 + s) * CCn * HW +
                    (size_t)(co0 + coloc) * HW + gh * Wn + gw] = fmaxf(y, 0.f);
            }
        }
        (void)obase;
    }
}

extern "C" void kernel_launch(void* const* d_in, const int* in_sizes, int n_in,
                              void* d_out, int out_size) {
    const float* u = (const float*)d_in[0];
    const float* v = (const float*)d_in[1];
    const float* w = (const float*)d_in[2];
    const float* g = (const float*)d_in[3];
    const float* bt = (const float*)d_in[4];
    const float* mn = (const float*)d_in[5];
    const float* vr = (const float*)d_in[6];

    dim3 grid(8, 32, 32);  // (w_tiles*co_halves, h_tiles, b*s images)
    cross_conv_kernel<<<grid, 256>>>(u, v, w, g, bt, mn, vr, (float*)d_out);
}

// round 5
// speedup vs baseline: 1.6019x; 1.1945x over previous
#include <cuda_runtime.h>
#include <cstdint>

// CrossConv2d fused: relu( BN(conv3x3(concat(u,v))) + concat(u,v) )
// u (4,1,64,128,128), v (4,8,64,128,128), w (128,128,3,3) OIHW, out fp32.
//
// Round 5 (= R4 resubmit after infra failure): double-buffered cp.async
// staging overlapped with compute.
//  - 2-stage pipeline, one barrier pair per ci-chunk, loads under compute.
//  - Input staged fp32 [ci][6][36]; splat via mov.b64 {x,x}.
//  - Weights staged 4B-grain transposed [rk][co] stride 66 -> compute reads
//    warp-uniform LDS.64 co-pairs.
//  - Inner loop fully unrolled: immediate smem offsets; FFMA2 dominant.

#define EPSV 1e-5f

constexpr int C1n = 64, CCn = 128, Hn = 128, Wn = 128, HW = Hn * Wn;
constexpr int CO_T = 64, H_T = 4, W_T = 32, CI_T = 8;
constexpr int NCHUNK = CCn / CI_T;  // 16

typedef unsigned long long u64;

__device__ __forceinline__ void ffma2(u64& d, u64 a, u64 b) {
    asm("fma.rn.f32x2 %0, %1, %2, %0;" : "+l"(d) : "l"(a), "l"(b));
}
__device__ __forceinline__ u64 splat2(float x) {
    u64 r;
    asm("mov.b64 %0, {%1, %1};" : "=l"(r) : "f"(x));
    return r;
}
__device__ __forceinline__ void unpack2(u64 p, float& lo, float& hi) {
    asm("mov.b64 {%0, %1}, %2;" : "=f"(lo), "=f"(hi) : "l"(p));
}
__device__ __forceinline__ void cp4(uint32_t dst, const float* src, bool ok) {
    int sz = ok ? 4 : 0;  // src-size 0 => zero-fill destination
    asm volatile("cp.async.ca.shared.global [%0], [%1], 4, %2;"
                 :: "r"(dst), "l"(src), "r"(sz));
}
__device__ __forceinline__ void cp_commit() { asm volatile("cp.async.commit_group;"); }
__device__ __forceinline__ void cp_wait0()  { asm volatile("cp.async.wait_group 0;"); }
__device__ __forceinline__ uint32_t saddr(const void* p) {
    return (uint32_t)__cvta_generic_to_shared(p);
}

__global__ __launch_bounds__(256, 2)
void cross_conv_kernel(const float* __restrict__ u, const float* __restrict__ v,
                       const float* __restrict__ w, const float* __restrict__ gma,
                       const float* __restrict__ bta, const float* __restrict__ mean,
                       const float* __restrict__ var, float* __restrict__ out) {
    __shared__ __align__(16) float s_in[2][CI_T][H_T + 2][36];
    __shared__ __align__(16) float s_w[2][72 * 66 + 8];

    const int tid = threadIdx.x;
    const int lane = tid & 31;
    const int warp = tid >> 5;
    const int img = blockIdx.z;
    const int b = img >> 3, s = img & 7;
    const int h0 = blockIdx.y * H_T;
    const int w0 = (blockIdx.x >> 1) * W_T;
    const int co0 = (blockIdx.x & 1) * CO_T;

    const float* ubase = u + (size_t)b * C1n * HW;
    const float* vbase = v + (size_t)(b * 8 + s) * C1n * HW;
    const float* wbase = w + (size_t)co0 * (CCn * 9);

    u64 acc[4][H_T];
#pragma unroll
    for (int a = 0; a < 4; a++)
#pragma unroll
        for (int c = 0; c < H_T; c++) acc[a][c] = 0ull;

#define STAGE(chunk_, buf_)                                                        \
    do {                                                                           \
        const int _ci0 = (chunk_)*CI_T;                                            \
        const float* _base = (_ci0 < C1n) ? ubase + (size_t)_ci0 * HW              \
                                          : vbase + (size_t)(_ci0 - C1n) * HW;     \
        const float* _sp = _base + (size_t)warp * HW;                              \
        const int _gw1 = w0 - 1 + lane;                                            \
        const bool _w1ok = (unsigned)_gw1 < (unsigned)Wn;                          \
        const int _gw2 = w0 + 31 + lane;                                           \
        const bool _w2ok = (unsigned)_gw2 < (unsigned)Wn;                          \
        _Pragma("unroll") for (int _r = 0; _r < H_T + 2; _r++) {                   \
            int _gh = h0 - 1 + _r;                                                 \
            bool _hok = (unsigned)_gh < (unsigned)Hn;                              \
            const float* _rowp = _sp + (_hok ? _gh : 0) * Wn;                      \
            bool _ok1 = _hok && _w1ok;                                             \
            cp4(saddr(&s_in[buf_][warp][_r][lane]),                                \
                _rowp + (_ok1 ? _gw1 : 0), _ok1);                                  \
            if (lane < 2) {                                                        \
                bool _ok2 = _hok && _w2ok;                                         \
                cp4(saddr(&s_in[buf_][warp][_r][lane + 32]),                       \
                    _rowp + (_ok2 ? _gw2 : 0), _ok2);                              \
            }                                                                      \
        }                                                                          \
        const float* _wchunk = wbase + (chunk_) * (CI_T * 9);                      \
        _Pragma("unroll") for (int _j = 0; _j < 8; _j++) {                         \
            int _co = warp * 8 + _j;                                               \
            const float* _wr = _wchunk + (size_t)_co * (CCn * 9);                  \
            cp4(saddr(&s_w[buf_][lane * 66 + _co]), _wr + lane, true);             \
            cp4(saddr(&s_w[buf_][(lane + 32) * 66 + _co]), _wr + lane + 32, true); \
            if (lane < 8)                                                          \
                cp4(saddr(&s_w[buf_][(lane + 64) * 66 + _co]), _wr + lane + 64,    \
                    true);                                                         \
        }                                                                          \
        cp_commit();                                                               \
    } while (0)

    STAGE(0, 0);

    for (int c = 0; c < NCHUNK; c++) {
        const int buf = c & 1;
        cp_wait0();
        __syncthreads();
        if (c + 1 < NCHUNK) STAGE(c + 1, buf ^ 1);

        // ---- compute chunk c ----
#pragma unroll
        for (int ci = 0; ci < CI_T; ci++) {
#pragma unroll
            for (int kw = 0; kw < 3; kw++) {
                u64 p[H_T + 2];
#pragma unroll
                for (int r = 0; r < H_T + 2; r++)
                    p[r] = splat2(s_in[buf][ci][r][lane + kw]);
#pragma unroll
                for (int kh = 0; kh < 3; kh++) {
                    const int rk = ci * 9 + kh * 3 + kw;
                    u64 wp[4];
#pragma unroll
                    for (int j2 = 0; j2 < 4; j2++)
                        wp[j2] = *reinterpret_cast<const u64*>(
                            &s_w[buf][rk * 66 + warp * 8 + 2 * j2]);
#pragma unroll
                    for (int j2 = 0; j2 < 4; j2++)
#pragma unroll
                        for (int hh = 0; hh < H_T; hh++)
                            ffma2(acc[j2][hh], wp[j2], p[kh + hh]);
                }
            }
        }
        __syncthreads();  // buf fully consumed before next refill targets it
    }

    // ---- epilogue: BN affine + identity skip + ReLU ----
    const int gw = w0 + lane;
    float sc[8], sh[8];
#pragma unroll
    for (int j = 0; j < 8; j++) {
        int co = co0 + warp * 8 + j;
        float scv = gma[co] * rsqrtf(var[co] + EPSV);
        sc[j] = scv;
        sh[j] = bta[co] - mean[co] * scv;
    }
    const float* skipb = co0 ? vbase : ubase;
    float* obase = out + (size_t)(b * 8 + s) * CCn * HW + (size_t)co0 * HW;
#pragma unroll
    for (int hh = 0; hh < H_T; hh++) {
        int gh = h0 + hh;
#pragma unroll
        for (int j2 = 0; j2 < 4; j2++) {
            float pv0, pv1;
            unpack2(acc[j2][hh], pv0, pv1);
            float pv[2] = {pv0, pv1};
#pragma unroll
            for (int t = 0; t < 2; t++) {
                int j = 2 * j2 + t;
                int coloc = warp * 8 + j;
                float skip = skipb[(size_t)coloc * HW + gh * Wn + gw];
                float y = pv[t] * sc[j] + sh[j] + skip;
                obase[(size_t)coloc * HW + gh * Wn + gw] = fmaxf(y, 0.f);
            }
        }
    }
}

extern "C" void kernel_launch(void* const* d_in, const int* in_sizes, int n_in,
                              void* d_out, int out_size) {
    const float* u = (const float*)d_in[0];
    const float* v = (const float*)d_in[1];
    const float* w = (const float*)d_in[2];
    const float* g = (const float*)d_in[3];
    const float* bt = (const float*)d_in[4];
    const float* mn = (const float*)d_in[5];
    const float* vr = (const float*)d_in[6];

    dim3 grid(8, 32, 32);
    cross_conv_kernel<<<grid, 256>>>(u, v, w, g, bt, mn, vr, (float*)d_out);
}

// round 9
// speedup vs baseline: 5.5055x; 3.4368x over previous
#include <cuda_runtime.h>
#include <cstdint>

// CrossConv2d fused via mma.sync tf32 implicit GEMM (tcgen05 unavailable:
// harness compiles to compute_103 without the 'a' suffix).
// out = relu( BN(conv3x3(concat(u,v))) + concat(u,v) )
// u (4,1,64,128,128), v (4,8,64,128,128), w (128,128,3,3) OIHW, out fp32.
//
// Per CTA: 128 co x 2 output rows x 128 cols. Warp grid 2(M) x 4(N):
// each warp 64co x 64pos, 128 fp32 accumulators, m16n8k8 tf32 mma.
// Weights pre-packed to fragment order (cvt.rna.tf32) -> A = 1x LDS.128.
// Input tile [8ci][4 halo rows][130] fp32; taps = smem index shifts.
// 2-stage cp.async double buffering (structure proven in R5).

typedef unsigned int u32;

constexpr int Hn = 128, Wn = 128, HW = Hn * Wn, C1 = 64;
constexpr int NCH = 16;                       // ci chunks of 8
constexpr int A_BYTES = 9 * 8 * 32 * 16;      // taps x mtiles x lanes x 16B = 36864
constexpr int B_FLOATS = 8 * 4 * 130;         // ci x halo-rows x pos = 4160
constexpr int B_BYTES = B_FLOATS * 4;         // 16640

constexpr int SM_SC = 0, SM_SH = 512;
constexpr int SM_A = 1024;
constexpr int SM_B = SM_A + 2 * A_BYTES;      // 74752
constexpr int SM_TOTAL = SM_B + 2 * B_BYTES;  // 108032

__device__ float g_wA[NCH * 9 * 8 * 32 * 4];  // fragment-ordered weights

__device__ __forceinline__ u32 s2u(const void* p) {
    return (u32)__cvta_generic_to_shared(p);
}
__device__ __forceinline__ void cp4(u32 dst, const float* src, bool ok) {
    int sz = ok ? 4 : 0;
    asm volatile("cp.async.ca.shared.global [%0], [%1], 4, %2;"
                 :: "r"(dst), "l"(src), "r"(sz));
}
__device__ __forceinline__ void cp16(u32 dst, const float* src) {
    asm volatile("cp.async.cg.shared.global [%0], [%1], 16;"
                 :: "r"(dst), "l"(src));
}
__device__ __forceinline__ void cp_commit() { asm volatile("cp.async.commit_group;"); }
__device__ __forceinline__ void cp_wait0()  { asm volatile("cp.async.wait_group 0;"); }

__device__ __forceinline__ u32 f2tf32(float x) {
    u32 r;
    asm("cvt.rna.tf32.f32 %0, %1;" : "=r"(r) : "f"(x));
    return r;
}
__device__ __forceinline__ void mma_tf32(float* d, const u32* a, const u32* b) {
    asm volatile(
        "mma.sync.aligned.m16n8k8.row.col.f32.tf32.tf32.f32 "
        "{%0,%1,%2,%3}, {%4,%5,%6,%7}, {%8,%9}, {%0,%1,%2,%3};"
        : "+f"(d[0]), "+f"(d[1]), "+f"(d[2]), "+f"(d[3])
        : "r"(a[0]), "r"(a[1]), "r"(a[2]), "r"(a[3]), "r"(b[0]), "r"(b[1]));
}

// ---- prep: w[co][ci][tap] -> fragment order, tf32-rounded ----
// g_wA[((cc*9 + tap)*8 + mt)*32 + lane][j]:
//  j=0:(g,c) j=1:(g+8,c) j=2:(g,c+4) j=3:(g+8,c+4); co=mt*16+g, ci=cc*8+c.
__global__ void wprep_kernel(const float* __restrict__ w) {
    int idx = blockIdx.x * 256 + threadIdx.x;   // 0..36863
    if (idx >= NCH * 9 * 8 * 32) return;
    int lane = idx & 31;
    int mt = (idx >> 5) & 7;
    int tap = (idx >> 8) % 9;
    int cc = idx / (9 * 8 * 32);
    int g = lane >> 2, c = lane & 3;
    int co = mt * 16 + g, ci = cc * 8 + c;
    u32* dst = (u32*)&g_wA[idx * 4];
    dst[0] = f2tf32(w[((size_t)co * 128 + ci) * 9 + tap]);
    dst[1] = f2tf32(w[((size_t)(co + 8) * 128 + ci) * 9 + tap]);
    dst[2] = f2tf32(w[((size_t)co * 128 + ci + 4) * 9 + tap]);
    dst[3] = f2tf32(w[((size_t)(co + 8) * 128 + ci + 4) * 9 + tap]);
}

__global__ __launch_bounds__(256, 1)
void conv_mma_kernel(const float* __restrict__ u, const float* __restrict__ v,
                     const float* __restrict__ gma, const float* __restrict__ bta,
                     const float* __restrict__ mean, const float* __restrict__ var,
                     float* __restrict__ out) {
    extern __shared__ __align__(16) char smem[];
    const u32 sbase = s2u(smem);
    const int tid = threadIdx.x, lane = tid & 31, warp = tid >> 5;
    const int wm = warp & 1;          // co half
    const int wn = warp >> 1;         // pos quarter
    const int row_l = wn >> 1;        // local output row 0/1
    const int colb = (wn & 1) * 64;   // column half
    const int img = blockIdx.y;
    const int b = img >> 3, s = img & 7;
    const int h0 = blockIdx.x * 2;

    const float* ub = u + (size_t)b * C1 * HW;
    const float* vb = v + (size_t)(b * 8 + s) * C1 * HW;

    if (tid < 128) {
        float scv = gma[tid] * rsqrtf(var[tid] + 1e-5f);
        ((float*)(smem + SM_SC))[tid] = scv;
        ((float*)(smem + SM_SH))[tid] = bta[tid] - mean[tid] * scv;
    }

    float d[4][8][4];
#pragma unroll
    for (int mt = 0; mt < 4; mt++)
#pragma unroll
        for (int nt = 0; nt < 8; nt++)
#pragma unroll
            for (int j = 0; j < 4; j++) d[mt][nt][j] = 0.f;

    // ---- staging: A contiguous cp16; B per-warp ci plane, 4 rows x 130 ----
    auto stage = [&](int chunk, int buf) {
        const float* asrc = g_wA + (size_t)chunk * (9 * 8 * 32 * 4);
        u32 adst = sbase + SM_A + buf * A_BYTES;
        for (int i = tid; i < A_BYTES / 16; i += 256) cp16(adst + i * 16, asrc + i * 4);

        int cich = chunk * 8 + warp;
        const float* base = (cich < C1) ? ub + (size_t)cich * HW
                                        : vb + (size_t)(cich - C1) * HW;
        u32 bb = sbase + SM_B + buf * B_BYTES + warp * (520 * 4);
#pragma unroll
        for (int hr = 0; hr < 4; hr++) {
            int gh = h0 - 1 + hr;
            bool hok = (unsigned)gh < (unsigned)Hn;
            const float* rowp = base + (hok ? gh : 0) * Wn;
#pragma unroll
            for (int pc = 0; pc < 5; pc++) {
                int pos = pc * 32 + lane;
                if (pc < 4 || lane < 2) {
                    int gw = pos - 1;
                    bool ok = hok && ((unsigned)gw < (unsigned)Wn);
                    cp4(bb + (hr * 130 + pos) * 4, rowp + (ok ? gw : 0), ok);
                }
            }
        }
        cp_commit();
    };

    stage(0, 0);

    for (int c = 0; c < NCH; c++) {
        const int buf = c & 1;
        cp_wait0();
        __syncthreads();
        if (c + 1 < NCH) stage(c + 1, buf ^ 1);

        const float* bB = (const float*)(smem + SM_B + buf * B_BYTES);
        const char* aB = smem + SM_A + buf * A_BYTES;
        const int g = lane >> 2, c4 = lane & 3;

#pragma unroll
        for (int kh = 0; kh < 3; kh++) {
#pragma unroll
            for (int kw = 0; kw < 3; kw++) {
                const int tap = kh * 3 + kw;
                // B fragments for all 8 n-tiles of this warp
                const int bbase = c4 * 520 + (row_l + kh) * 130 + colb + g + kw;
                u32 bf[8][2];
#pragma unroll
                for (int nt = 0; nt < 8; nt++) {
                    bf[nt][0] = __float_as_uint(bB[bbase + nt * 8]);
                    bf[nt][1] = __float_as_uint(bB[bbase + nt * 8 + 4 * 520]);
                }
#pragma unroll
                for (int mt = 0; mt < 4; mt++) {
                    uint4 av = *(const uint4*)(aB +
                        (((tap * 8) + wm * 4 + mt) * 32 + lane) * 16);
                    u32 af[4] = {av.x, av.y, av.z, av.w};
#pragma unroll
                    for (int nt = 0; nt < 8; nt++) mma_tf32(d[mt][nt], af, bf[nt]);
                }
            }
        }
        __syncthreads();
    }

    // ---- epilogue: BN + skip + ReLU, float2 stores ----
    const float* sc_t = (const float*)(smem + SM_SC);
    const float* sh_t = (const float*)(smem + SM_SH);
    float* outb = out + (size_t)(b * 8 + s) * 128 * HW;
    const int g = lane >> 2, c4 = lane & 3;
    const int gh = h0 + row_l;

#pragma unroll
    for (int mt = 0; mt < 4; mt++) {
#pragma unroll
        for (int half = 0; half < 2; half++) {       // c0/c1 vs c2/c3
            int co = wm * 64 + mt * 16 + g + half * 8;
            const float* sk = (co < C1) ? ub + (size_t)co * HW
                                        : vb + (size_t)(co - C1) * HW;
            float scv = sc_t[co], shv = sh_t[co];
#pragma unroll
            for (int nt = 0; nt < 8; nt++) {
                int col = colb + nt * 8 + c4 * 2;
                float2 skv = *(const float2*)(sk + gh * Wn + col);
                float y0 = d[mt][nt][half * 2 + 0] * scv + shv + skv.x;
                float y1 = d[mt][nt][half * 2 + 1] * scv + shv + skv.y;
                *(float2*)(outb + (size_t)co * HW + gh * Wn + col) =
                    make_float2(fmaxf(y0, 0.f), fmaxf(y1, 0.f));
            }
        }
    }
}

extern "C" void kernel_launch(void* const* d_in, const int* in_sizes, int n_in,
                              void* d_out, int out_size) {
    const float* u = (const float*)d_in[0];
    const float* v = (const float*)d_in[1];
    const float* w = (const float*)d_in[2];
    const float* g = (const float*)d_in[3];
    const float* bt = (const float*)d_in[4];
    const float* mn = (const float*)d_in[5];
    const float* vr = (const float*)d_in[6];

    cudaFuncSetAttribute(conv_mma_kernel,
                         cudaFuncAttributeMaxDynamicSharedMemorySize, SM_TOTAL);

    wprep_kernel<<<144, 256>>>(w);
    dim3 grid(64, 32);  // (row pairs, images)
    conv_mma_kernel<<<grid, 256, SM_TOTAL>>>(u, v, g, bt, mn, vr, (float*)d_out);
}

// round 10
// speedup vs baseline: 5.5213x; 1.0029x over previous
#include <cuda_runtime.h>
#include <cstdint>

// CrossConv2d fused via mma.sync tf32 implicit GEMM (tcgen05 unavailable on
// this toolchain's compute_103 target).
// out = relu( BN(conv3x3(concat(u,v))) + concat(u,v) )
//
// R10 vs R9: CI_T 8->16 (8 chunks, halved barrier events), single
// __syncthreads per chunk (wait -> sync -> restage freed buffer -> compute).
// Per CTA: 128 co x 2 rows x 128 cols; warp = 64co x 64pos, 128 accums.

typedef unsigned int u32;

constexpr int Hn = 128, Wn = 128, HW = Hn * Wn, C1 = 64;
constexpr int NCH = 8;                          // ci chunks of 16
constexpr int A_BYTES = 9 * 2 * 8 * 32 * 16;    // taps x kt x mtiles x lanes x 16B = 73728
constexpr int B_FLOATS = 16 * 520;              // 16 ci planes x (4 rows x 130)
constexpr int B_BYTES = B_FLOATS * 4;           // 33280

constexpr int SM_SC = 0, SM_SH = 512;
constexpr int SM_A = 1024;
constexpr int SM_B = SM_A + 2 * A_BYTES;        // 148480
constexpr int SM_TOTAL = SM_B + 2 * B_BYTES;    // 215040 (210KB)

__device__ float g_wA[8 * 9 * 2 * 8 * 32 * 4];  // fragment-ordered weights

__device__ __forceinline__ u32 s2u(const void* p) {
    return (u32)__cvta_generic_to_shared(p);
}
__device__ __forceinline__ void cp4(u32 dst, const float* src, bool ok) {
    int sz = ok ? 4 : 0;
    asm volatile("cp.async.ca.shared.global [%0], [%1], 4, %2;"
                 :: "r"(dst), "l"(src), "r"(sz));
}
__device__ __forceinline__ void cp16(u32 dst, const float* src) {
    asm volatile("cp.async.cg.shared.global [%0], [%1], 16;"
                 :: "r"(dst), "l"(src));
}
__device__ __forceinline__ void cp_commit() { asm volatile("cp.async.commit_group;"); }
__device__ __forceinline__ void cp_wait0()  { asm volatile("cp.async.wait_group 0;"); }

__device__ __forceinline__ u32 f2tf32(float x) {
    u32 r;
    asm("cvt.rna.tf32.f32 %0, %1;" : "=r"(r) : "f"(x));
    return r;
}
__device__ __forceinline__ void mma_tf32(float* d, const u32* a, const u32* b) {
    asm volatile(
        "mma.sync.aligned.m16n8k8.row.col.f32.tf32.tf32.f32 "
        "{%0,%1,%2,%3}, {%4,%5,%6,%7}, {%8,%9}, {%0,%1,%2,%3};"
        : "+f"(d[0]), "+f"(d[1]), "+f"(d[2]), "+f"(d[3])
        : "r"(a[0]), "r"(a[1]), "r"(a[2]), "r"(a[3]), "r"(b[0]), "r"(b[1]));
}

// ---- prep: w[co][ci][tap] -> fragment order, tf32-rounded ----
// Layout: [cc(8)][tap(9)][kt(2)][mt(8)][lane(32)][4 regs]
// lane: g=lane>>2 (row-in-tile), c=lane&3 (k-in-ktile)
// co = mt*16+g (+8 for regs 1,3); ci = cc*16 + kt*8 + c (+4 for regs 2,3)
__global__ void wprep_kernel(const float* __restrict__ w) {
    int idx = blockIdx.x * 256 + threadIdx.x;   // 0..36863
    if (idx >= 8 * 9 * 2 * 8 * 32) return;
    int lane = idx & 31;
    int mt = (idx >> 5) & 7;
    int kt = (idx >> 8) & 1;
    int tap = (idx >> 9) % 9;
    int cc = idx / (9 * 2 * 8 * 32);
    int g = lane >> 2, c = lane & 3;
    int co = mt * 16 + g;
    int ci = cc * 16 + kt * 8 + c;
    u32* dst = (u32*)&g_wA[idx * 4];
    dst[0] = f2tf32(w[((size_t)co * 128 + ci) * 9 + tap]);
    dst[1] = f2tf32(w[((size_t)(co + 8) * 128 + ci) * 9 + tap]);
    dst[2] = f2tf32(w[((size_t)co * 128 + ci + 4) * 9 + tap]);
    dst[3] = f2tf32(w[((size_t)(co + 8) * 128 + ci + 4) * 9 + tap]);
}

__global__ __launch_bounds__(256, 1)
void conv_mma_kernel(const float* __restrict__ u, const float* __restrict__ v,
                     const float* __restrict__ gma, const float* __restrict__ bta,
                     const float* __restrict__ mean, const float* __restrict__ var,
                     float* __restrict__ out) {
    extern __shared__ __align__(16) char smem[];
    const u32 sbase = s2u(smem);
    const int tid = threadIdx.x, lane = tid & 31, warp = tid >> 5;
    const int wm = warp & 1;
    const int wn = warp >> 1;
    const int row_l = wn >> 1;
    const int colb = (wn & 1) * 64;
    const int img = blockIdx.y;
    const int b = img >> 3, s = img & 7;
    const int h0 = blockIdx.x * 2;

    const float* ub = u + (size_t)b * C1 * HW;
    const float* vb = v + (size_t)(b * 8 + s) * C1 * HW;

    if (tid < 128) {
        float scv = gma[tid] * rsqrtf(var[tid] + 1e-5f);
        ((float*)(smem + SM_SC))[tid] = scv;
        ((float*)(smem + SM_SH))[tid] = bta[tid] - mean[tid] * scv;
    }

    float d[4][8][4];
#pragma unroll
    for (int mt = 0; mt < 4; mt++)
#pragma unroll
        for (int nt = 0; nt < 8; nt++)
#pragma unroll
            for (int j = 0; j < 4; j++) d[mt][nt][j] = 0.f;

    // ---- staging: A contiguous cp16; B = 2 ci planes per warp ----
    auto stage = [&](int chunk, int buf) {
        const float* asrc = g_wA + (size_t)chunk * (A_BYTES / 4);
        u32 adst = sbase + SM_A + buf * A_BYTES;
        for (int i = tid; i < A_BYTES / 16; i += 256) cp16(adst + i * 16, asrc + i * 4);

#pragma unroll
        for (int pl = 0; pl < 2; pl++) {
            int cil = warp + pl * 8;                  // 0..15 within chunk
            int cich = chunk * 16 + cil;
            const float* base = (cich < C1) ? ub + (size_t)cich * HW
                                            : vb + (size_t)(cich - C1) * HW;
            u32 bb = sbase + SM_B + buf * B_BYTES + cil * (520 * 4);
#pragma unroll
            for (int hr = 0; hr < 4; hr++) {
                int gh = h0 - 1 + hr;
                bool hok = (unsigned)gh < (unsigned)Hn;
                const float* rowp = base + (hok ? gh : 0) * Wn;
#pragma unroll
                for (int pc = 0; pc < 5; pc++) {
                    int pos = pc * 32 + lane;
                    if (pc < 4 || lane < 2) {
                        int gw = pos - 1;
                        bool ok = hok && ((unsigned)gw < (unsigned)Wn);
                        cp4(bb + (hr * 130 + pos) * 4, rowp + (ok ? gw : 0), ok);
                    }
                }
            }
        }
        cp_commit();
    };

    stage(0, 0);

    const int g = lane >> 2, c4 = lane & 3;
    for (int c = 0; c < NCH; c++) {
        const int buf = c & 1;
        cp_wait0();            // chunk c landed (staged one full chunk ago)
        __syncthreads();       // all warps done with buf^1 (chunk c-1)
        if (c + 1 < NCH) stage(c + 1, buf ^ 1);

        const float* bB = (const float*)(smem + SM_B + buf * B_BYTES);
        const char* aB = smem + SM_A + buf * A_BYTES;

#pragma unroll
        for (int kh = 0; kh < 3; kh++) {
#pragma unroll
            for (int kw = 0; kw < 3; kw++) {
                const int tap = kh * 3 + kw;
#pragma unroll
                for (int kt = 0; kt < 2; kt++) {
                    const int bbase = (kt * 8 + c4) * 520 + (row_l + kh) * 130 +
                                      colb + g + kw;
                    u32 bf[8][2];
#pragma unroll
                    for (int nt = 0; nt < 8; nt++) {
                        bf[nt][0] = __float_as_uint(bB[bbase + nt * 8]);
                        bf[nt][1] = __float_as_uint(bB[bbase + nt * 8 + 4 * 520]);
                    }
#pragma unroll
                    for (int mt = 0; mt < 4; mt++) {
                        uint4 av = *(const uint4*)(aB +
                            ((((tap * 2) + kt) * 8 + wm * 4 + mt) * 32 + lane) * 16);
                        u32 af[4] = {av.x, av.y, av.z, av.w};
#pragma unroll
                        for (int nt = 0; nt < 8; nt++) mma_tf32(d[mt][nt], af, bf[nt]);
                    }
                }
            }
        }
    }

    // ---- epilogue: BN + skip + ReLU, float2 stores ----
    const float* sc_t = (const float*)(smem + SM_SC);
    const float* sh_t = (const float*)(smem + SM_SH);
    float* outb = out + (size_t)(b * 8 + s) * 128 * HW;
    const int gh = h0 + row_l;

#pragma unroll
    for (int mt = 0; mt < 4; mt++) {
#pragma unroll
        for (int half = 0; half < 2; half++) {
            int co = wm * 64 + mt * 16 + g + half * 8;
            const float* sk = (co < C1) ? ub + (size_t)co * HW
                                        : vb + (size_t)(co - C1) * HW;
            float scv = sc_t[co], shv = sh_t[co];
#pragma unroll
            for (int nt = 0; nt < 8; nt++) {
                int col = colb + nt * 8 + c4 * 2;
                float2 skv = *(const float2*)(sk + gh * Wn + col);
                float y0 = d[mt][nt][half * 2 + 0] * scv + shv + skv.x;
                float y1 = d[mt][nt][half * 2 + 1] * scv + shv + skv.y;
                *(float2*)(outb + (size_t)co * HW + gh * Wn + col) =
                    make_float2(fmaxf(y0, 0.f), fmaxf(y1, 0.f));
            }
        }
    }
}

extern "C" void kernel_launch(void* const* d_in, const int* in_sizes, int n_in,
                              void* d_out, int out_size) {
    const float* u = (const float*)d_in[0];
    const float* v = (const float*)d_in[1];
    const float* w = (const float*)d_in[2];
    const float* g = (const float*)d_in[3];
    const float* bt = (const float*)d_in[4];
    const float* mn = (const float*)d_in[5];
    const float* vr = (const float*)d_in[6];

    cudaFuncSetAttribute(conv_mma_kernel,
                         cudaFuncAttributeMaxDynamicSharedMemorySize, SM_TOTAL);

    wprep_kernel<<<144, 256>>>(w);
    dim3 grid(64, 32);  // (row pairs, images)
    conv_mma_kernel<<<grid, 256, SM_TOTAL>>>(u, v, g, bt, mn, vr, (float*)d_out);
}

// round 12
// speedup vs baseline: 5.8765x; 1.0643x over previous
#include <cuda_runtime.h>
#include <cstdint>

// CrossConv2d fused via mma.sync tf32 implicit GEMM.
// out = relu( BN(conv3x3(concat(u,v))) + concat(u,v) )
//
// R11 vs R10: 512 threads / 16 warps per CTA, 64 accumulators per thread
// (was 256 thr / 128 acc / 254 regs = full RF at 8 warps). Doubles the
// latency-hiding warp pool and gives ptxas register headroom to hoist
// LDS fragment loads over HMMA groups. CTA tile unchanged: 128co x 2rows
// x 128cols; warp = 64co x 32pos (mt=4, nt=4).

typedef unsigned int u32;

constexpr int Hn = 128, Wn = 128, HW = Hn * Wn, C1 = 64;
constexpr int NCH = 8;                          // ci chunks of 16
constexpr int A_BYTES = 9 * 2 * 8 * 32 * 16;    // 73728
constexpr int B_FLOATS = 16 * 520;
constexpr int B_BYTES = B_FLOATS * 4;           // 33280

constexpr int SM_SC = 0, SM_SH = 512;
constexpr int SM_A = 1024;
constexpr int SM_B = SM_A + 2 * A_BYTES;
constexpr int SM_TOTAL = SM_B + 2 * B_BYTES;    // 215040

__device__ float g_wA[8 * 9 * 2 * 8 * 32 * 4];

__device__ __forceinline__ u32 s2u(const void* p) {
    return (u32)__cvta_generic_to_shared(p);
}
__device__ __forceinline__ void cp4(u32 dst, const float* src, bool ok) {
    int sz = ok ? 4 : 0;
    asm volatile("cp.async.ca.shared.global [%0], [%1], 4, %2;"
                 :: "r"(dst), "l"(src), "r"(sz));
}
__device__ __forceinline__ void cp16(u32 dst, const float* src) {
    asm volatile("cp.async.cg.shared.global [%0], [%1], 16;"
                 :: "r"(dst), "l"(src));
}
__device__ __forceinline__ void cp_commit() { asm volatile("cp.async.commit_group;"); }
__device__ __forceinline__ void cp_wait0()  { asm volatile("cp.async.wait_group 0;"); }

__device__ __forceinline__ u32 f2tf32(float x) {
    u32 r;
    asm("cvt.rna.tf32.f32 %0, %1;" : "=r"(r) : "f"(x));
    return r;
}
__device__ __forceinline__ void mma_tf32(float* d, const u32* a, const u32* b) {
    asm volatile(
        "mma.sync.aligned.m16n8k8.row.col.f32.tf32.tf32.f32 "
        "{%0,%1,%2,%3}, {%4,%5,%6,%7}, {%8,%9}, {%0,%1,%2,%3};"
        : "+f"(d[0]), "+f"(d[1]), "+f"(d[2]), "+f"(d[3])
        : "r"(a[0]), "r"(a[1]), "r"(a[2]), "r"(a[3]), "r"(b[0]), "r"(b[1]));
}

// prep: w[co][ci][tap] -> fragment order [cc][tap][kt][mt][lane][4], tf32.
__global__ void wprep_kernel(const float* __restrict__ w) {
    int idx = blockIdx.x * 256 + threadIdx.x;
    if (idx >= 8 * 9 * 2 * 8 * 32) return;
    int lane = idx & 31;
    int mt = (idx >> 5) & 7;
    int kt = (idx >> 8) & 1;
    int tap = (idx >> 9) % 9;
    int cc = idx / (9 * 2 * 8 * 32);
    int g = lane >> 2, c = lane & 3;
    int co = mt * 16 + g;
    int ci = cc * 16 + kt * 8 + c;
    u32* dst = (u32*)&g_wA[idx * 4];
    dst[0] = f2tf32(w[((size_t)co * 128 + ci) * 9 + tap]);
    dst[1] = f2tf32(w[((size_t)(co + 8) * 128 + ci) * 9 + tap]);
    dst[2] = f2tf32(w[((size_t)co * 128 + ci + 4) * 9 + tap]);
    dst[3] = f2tf32(w[((size_t)(co + 8) * 128 + ci + 4) * 9 + tap]);
}

__global__ __launch_bounds__(512, 1)
void conv_mma_kernel(const float* __restrict__ u, const float* __restrict__ v,
                     const float* __restrict__ gma, const float* __restrict__ bta,
                     const float* __restrict__ mean, const float* __restrict__ var,
                     float* __restrict__ out) {
    extern __shared__ __align__(16) char smem[];
    const u32 sbase = s2u(smem);
    const int tid = threadIdx.x, lane = tid & 31, warp = tid >> 5;   // 16 warps
    const int wm = warp & 1;              // co half (64)
    const int wq = (warp >> 1) & 3;       // col quarter (32)
    const int row_l = warp >> 3;          // local output row 0/1
    const int colb = wq * 32;
    const int img = blockIdx.y;
    const int b = img >> 3, s = img & 7;
    const int h0 = blockIdx.x * 2;

    const float* ub = u + (size_t)b * C1 * HW;
    const float* vb = v + (size_t)(b * 8 + s) * C1 * HW;

    if (tid < 128) {
        float scv = gma[tid] * rsqrtf(var[tid] + 1e-5f);
        ((float*)(smem + SM_SC))[tid] = scv;
        ((float*)(smem + SM_SH))[tid] = bta[tid] - mean[tid] * scv;
    }

    float d[4][4][4];   // [mt][nt][frag]
#pragma unroll
    for (int mt = 0; mt < 4; mt++)
#pragma unroll
        for (int nt = 0; nt < 4; nt++)
#pragma unroll
            for (int j = 0; j < 4; j++) d[mt][nt][j] = 0.f;

    // staging: A spread over 512 threads; B: warp w stages ci plane w.
    auto stage = [&](int chunk, int buf) {
        const float* asrc = g_wA + (size_t)chunk * (A_BYTES / 4);
        u32 adst = sbase + SM_A + buf * A_BYTES;
        for (int i = tid; i < A_BYTES / 16; i += 512) cp16(adst + i * 16, asrc + i * 4);

        int cich = chunk * 16 + warp;
        const float* base = (cich < C1) ? ub + (size_t)cich * HW
                                        : vb + (size_t)(cich - C1) * HW;
        u32 bb = sbase + SM_B + buf * B_BYTES + warp * (520 * 4);
#pragma unroll
        for (int hr = 0; hr < 4; hr++) {
            int gh = h0 - 1 + hr;
            bool hok = (unsigned)gh < (unsigned)Hn;
            const float* rowp = base + (hok ? gh : 0) * Wn;
#pragma unroll
            for (int pc = 0; pc < 5; pc++) {
                int pos = pc * 32 + lane;
                if (pc < 4 || lane < 2) {
                    int gw = pos - 1;
                    bool ok = hok && ((unsigned)gw < (unsigned)Wn);
                    cp4(bb + (hr * 130 + pos) * 4, rowp + (ok ? gw : 0), ok);
                }
            }
        }
        cp_commit();
    };

    stage(0, 0);

    const int g = lane >> 2, c4 = lane & 3;
    for (int c = 0; c < NCH; c++) {
        const int buf = c & 1;
        cp_wait0();
        __syncthreads();
        if (c + 1 < NCH) stage(c + 1, buf ^ 1);

        const float* bB = (const float*)(smem + SM_B + buf * B_BYTES);
        const char* aB = smem + SM_A + buf * A_BYTES;

#pragma unroll
        for (int kh = 0; kh < 3; kh++) {
#pragma unroll
            for (int kw = 0; kw < 3; kw++) {
                const int tap = kh * 3 + kw;
#pragma unroll
                for (int kt = 0; kt < 2; kt++) {
                    const int bbase = (kt * 8 + c4) * 520 + (row_l + kh) * 130 +
                                      colb + g + kw;
                    u32 bf[4][2];
#pragma unroll
                    for (int nt = 0; nt < 4; nt++) {
                        bf[nt][0] = __float_as_uint(bB[bbase + nt * 8]);
                        bf[nt][1] = __float_as_uint(bB[bbase + nt * 8 + 4 * 520]);
                    }
#pragma unroll
                    for (int mt = 0; mt < 4; mt++) {
                        uint4 av = *(const uint4*)(aB +
                            ((((tap * 2) + kt) * 8 + wm * 4 + mt) * 32 + lane) * 16);
                        u32 af[4] = {av.x, av.y, av.z, av.w};
#pragma unroll
                        for (int nt = 0; nt < 4; nt++) mma_tf32(d[mt][nt], af, bf[nt]);
                    }
                }
            }
        }
    }

    // epilogue: BN + skip + ReLU, float2 stores
    const float* sc_t = (const float*)(smem + SM_SC);
    const float* sh_t = (const float*)(smem + SM_SH);
    float* outb = out + (size_t)(b * 8 + s) * 128 * HW;
    const int gh = h0 + row_l;

#pragma unroll
    for (int mt = 0; mt < 4; mt++) {
#pragma unroll
        for (int half = 0; half < 2; half++) {
            int co = wm * 64 + mt * 16 + g + half * 8;
            const float* sk = (co < C1) ? ub + (size_t)co * HW
                                        : vb + (size_t)(co - C1) * HW;
            float scv = sc_t[co], shv = sh_t[co];
#pragma unroll
            for (int nt = 0; nt < 4; nt++) {
                int col = colb + nt * 8 + c4 * 2;
                float2 skv = *(const float2*)(sk + gh * Wn + col);
                float y0 = d[mt][nt][half * 2 + 0] * scv + shv + skv.x;
                float y1 = d[mt][nt][half * 2 + 1] * scv + shv + skv.y;
                *(float2*)(outb + (size_t)co * HW + gh * Wn + col) =
                    make_float2(fmaxf(y0, 0.f), fmaxf(y1, 0.f));
            }
        }
    }
}

extern "C" void kernel_launch(void* const* d_in, const int* in_sizes, int n_in,
                              void* d_out, int out_size) {
    const float* u = (const float*)d_in[0];
    const float* v = (const float*)d_in[1];
    const float* w = (const float*)d_in[2];
    const float* g = (const float*)d_in[3];
    const float* bt = (const float*)d_in[4];
    const float* mn = (const float*)d_in[5];
    const float* vr = (const float*)d_in[6];

    cudaFuncSetAttribute(conv_mma_kernel,
                         cudaFuncAttributeMaxDynamicSharedMemorySize, SM_TOTAL);

    wprep_kernel<<<144, 256>>>(w);
    dim3 grid(64, 32);  // (row pairs, images)
    conv_mma_kernel<<<grid, 512, SM_TOTAL>>>(u, v, g, bt, mn, vr, (float*)d_out);
}

// round 17
// speedup vs baseline: 9.9038x; 1.6853x over previous
#include <cuda_runtime.h>
#include <cuda_fp16.h>
#include <cstdint>

// CrossConv2d fused via mma.sync fp16 (m16n8k16) implicit GEMM.
// out = relu( BN(conv3x3(concat(u,v))) + concat(u,v) )
// fp16 has the same 11-bit significand as tf32 -> same ~4e-4 rel_err, but
// 2x MACs per HMMA and half the LDS bytes per MAC.
// R15 = R14 with the nonexistent __half2_as_uint replaced by manual
// ushort packing (this compile error was R13/R14's actual failure).
//
// Prep kernels: (1) weights -> fp16 fragment order, (2,3) u,v -> half2
// channel-pair-interleaved planes in __device__ scratch.
// Main: per CTA 128co x 2rows x 128cols; 512 thr / 16 warps; warp =
// 64co x 32pos (mt=4, nt=4); chunk = 16 ci = one k16 MMA per tap.
// Skip path reads original fp32 (epilogue exact).

typedef unsigned int u32;

constexpr int Hn = 128, Wn = 128, HW = Hn * Wn, C1 = 64;
constexpr int NCH = 8;                        // chunks of 16 ci (8 cipairs)
constexpr int A_BYTES = 9 * 8 * 32 * 16;      // taps x mt x lane x 16B = 36864
constexpr int B_BYTES = 8 * 520 * 4;          // cipair x (4rows x 130) x half2

constexpr int SM_SC = 0, SM_SH = 512;
constexpr int SM_A = 1024;
constexpr int SM_B = SM_A + 2 * A_BYTES;      // 74752
constexpr int SM_TOTAL = SM_B + 2 * B_BYTES;  // 108032

constexpr int UPREP_N = 4 * 32 * HW;          // 2097152
constexpr int VPREP_N = 32 * 32 * HW;         // 16777216

__device__ u32 g_wA[8 * 9 * 8 * 32 * 4];        // fp16x2 fragment weights
__device__ __half2 g_uh2[UPREP_N];              // u: [b][cipair][h][w]
__device__ __half2 g_vh2[VPREP_N];              // v: [img][cipair][h][w]

__device__ __forceinline__ u32 s2u(const void* p) {
    return (u32)__cvta_generic_to_shared(p);
}
__device__ __forceinline__ void cp4(u32 dst, const void* src, bool ok) {
    int sz = ok ? 4 : 0;
    asm volatile("cp.async.ca.shared.global [%0], [%1], 4, %2;"
                 :: "r"(dst), "l"(src), "r"(sz));
}
__device__ __forceinline__ void cp16(u32 dst, const void* src) {
    asm volatile("cp.async.cg.shared.global [%0], [%1], 16;"
                 :: "r"(dst), "l"(src));
}
__device__ __forceinline__ void cp_commit() { asm volatile("cp.async.commit_group;"); }
__device__ __forceinline__ void cp_wait0()  { asm volatile("cp.async.wait_group 0;"); }

__device__ __forceinline__ void mma_f16(float* d, const u32* a, const u32* b) {
    asm volatile(
        "mma.sync.aligned.m16n8k16.row.col.f32.f16.f16.f32 "
        "{%0,%1,%2,%3}, {%4,%5,%6,%7}, {%8,%9}, {%0,%1,%2,%3};"
        : "+f"(d[0]), "+f"(d[1]), "+f"(d[2]), "+f"(d[3])
        : "r"(a[0]), "r"(a[1]), "r"(a[2]), "r"(a[3]), "r"(b[0]), "r"(b[1]));
}

// pack two fp16 (as fp32 inputs) into one u32: lo in bits[0:16), hi above.
__device__ __forceinline__ u32 packh2(float lo, float hi) {
    unsigned short l = __half_as_ushort(__float2half(lo));
    unsigned short h = __half_as_ushort(__float2half(hi));
    return (u32)l | ((u32)h << 16);
}

// ---- prep 1: weights -> fragment order [cc][tap][mt][lane][4 x fp16x2] ----
// a0=(co, ci0|ci0+1) a1=(co+8, ..) a2=(co, ci0+8|+9) a3=(co+8, ..)
__global__ void wprep_kernel(const float* __restrict__ w) {
    int idx = blockIdx.x * 256 + threadIdx.x;   // 0..18431
    if (idx >= 8 * 9 * 8 * 32) return;
    int lane = idx & 31;
    int mt = (idx >> 5) & 7;
    int tap = (idx >> 8) % 9;
    int cc = idx / (9 * 8 * 32);
    int g = lane >> 2, c4 = lane & 3;
    int co = mt * 16 + g;
    int ci0 = cc * 16 + 2 * c4;
    u32* dst = &g_wA[idx * 4];
    auto wv = [&](int coo, int cii) {
        return w[((size_t)coo * 128 + cii) * 9 + tap];
    };
    dst[0] = packh2(wv(co, ci0), wv(co, ci0 + 1));
    dst[1] = packh2(wv(co + 8, ci0), wv(co + 8, ci0 + 1));
    dst[2] = packh2(wv(co, ci0 + 8), wv(co, ci0 + 9));
    dst[3] = packh2(wv(co + 8, ci0 + 8), wv(co + 8, ci0 + 9));
}

// ---- prep 2/3: activations -> half2 cipair-interleaved ----
__global__ void uprep_kernel(const float* __restrict__ u) {
    int idx = blockIdx.x * 256 + threadIdx.x;
    if (idx >= UPREP_N) return;
    int hw = idx & (HW - 1);
    int cp = (idx >> 14) & 31;
    int b = idx >> 19;
    const float* base = u + ((size_t)b * 64 + 2 * cp) * HW + hw;
    g_uh2[idx] = __halves2half2(__float2half(base[0]), __float2half(base[HW]));
}
__global__ void vprep_kernel(const float* __restrict__ v) {
    int idx = blockIdx.x * 256 + threadIdx.x;
    if (idx >= VPREP_N) return;
    int hw = idx & (HW - 1);
    int cp = (idx >> 14) & 31;
    int img = idx >> 19;
    const float* base = v + ((size_t)img * 64 + 2 * cp) * HW + hw;
    g_vh2[idx] = __halves2half2(__float2half(base[0]), __float2half(base[HW]));
}

__global__ __launch_bounds__(512, 1)
void conv_mma_kernel(const float* __restrict__ u, const float* __restrict__ v,
                     const float* __restrict__ gma, const float* __restrict__ bta,
                     const float* __restrict__ mean, const float* __restrict__ var,
                     float* __restrict__ out) {
    extern __shared__ __align__(16) char smem[];
    const u32 sbase = s2u(smem);
    const int tid = threadIdx.x, lane = tid & 31, warp = tid >> 5;
    const int wm = warp & 1;              // co half
    const int wq = (warp >> 1) & 3;       // col quarter
    const int row_l = warp >> 3;          // local output row
    const int colb = wq * 32;
    const int img = blockIdx.y;
    const int b = img >> 3;
    const int h0 = blockIdx.x * 2;

    const float* ub = u + (size_t)b * C1 * HW;
    const float* vb = v + (size_t)img * C1 * HW;
    const __half2* uh = g_uh2 + (size_t)b * 32 * HW;
    const __half2* vh = g_vh2 + (size_t)img * 32 * HW;

    if (tid < 128) {
        float scv = gma[tid] * rsqrtf(var[tid] + 1e-5f);
        ((float*)(smem + SM_SC))[tid] = scv;
        ((float*)(smem + SM_SH))[tid] = bta[tid] - mean[tid] * scv;
    }

    float d[4][4][4];
#pragma unroll
    for (int mt = 0; mt < 4; mt++)
#pragma unroll
        for (int nt = 0; nt < 4; nt++)
#pragma unroll
            for (int j = 0; j < 4; j++) d[mt][nt][j] = 0.f;

    // staging: A over all 512 thr; B: warp pair per cipair (2 rows each).
    auto stage = [&](int chunk, int buf) {
        const char* asrc = (const char*)g_wA + (size_t)chunk * A_BYTES;
        u32 adst = sbase + SM_A + buf * A_BYTES;
        for (int i = tid; i < A_BYTES / 16; i += 512) cp16(adst + i * 16, asrc + i * 16);

        int cp = warp >> 1;                        // 0..7
        int rhalf = warp & 1;
        int cpg = chunk * 8 + cp;                  // concat cipair 0..63
        const __half2* base = (cpg < 32) ? uh + (size_t)cpg * HW
                                         : vh + (size_t)(cpg - 32) * HW;
        u32 bb = sbase + SM_B + buf * B_BYTES + cp * (520 * 4);
#pragma unroll
        for (int hr2 = 0; hr2 < 2; hr2++) {
            int hr = rhalf * 2 + hr2;
            int gh = h0 - 1 + hr;
            bool hok = (unsigned)gh < (unsigned)Hn;
            const __half2* rowp = base + (hok ? gh : 0) * Wn;
#pragma unroll
            for (int pc = 0; pc < 5; pc++) {
                int pos = pc * 32 + lane;
                if (pc < 4 || lane < 2) {
                    int gw = pos - 1;
                    bool ok = hok && ((unsigned)gw < (unsigned)Wn);
                    cp4(bb + (hr * 130 + pos) * 4, rowp + (ok ? gw : 0), ok);
                }
            }
        }
        cp_commit();
    };

    stage(0, 0);

    const int g = lane >> 2, c4 = lane & 3;
    for (int c = 0; c < NCH; c++) {
        const int buf = c & 1;
        cp_wait0();
        __syncthreads();
        if (c + 1 < NCH) stage(c + 1, buf ^ 1);

        const u32* bB = (const u32*)(smem + SM_B + buf * B_BYTES);
        const char* aB = smem + SM_A + buf * A_BYTES;

#pragma unroll
        for (int kh = 0; kh < 3; kh++) {
#pragma unroll
            for (int kw = 0; kw < 3; kw++) {
                const int tap = kh * 3 + kw;
                const int bbase = c4 * 520 + (row_l + kh) * 130 + colb + g + kw;
                u32 bf[4][2];
#pragma unroll
                for (int nt = 0; nt < 4; nt++) {
                    bf[nt][0] = bB[bbase + nt * 8];
                    bf[nt][1] = bB[bbase + nt * 8 + 4 * 520];
                }
#pragma unroll
                for (int mt = 0; mt < 4; mt++) {
                    uint4 av = *(const uint4*)(aB +
                        ((tap * 8 + wm * 4 + mt) * 32 + lane) * 16);
                    u32 af[4] = {av.x, av.y, av.z, av.w};
#pragma unroll
                    for (int nt = 0; nt < 4; nt++) mma_f16(d[mt][nt], af, bf[nt]);
                }
            }
        }
    }

    // epilogue: BN + skip(fp32) + ReLU, float2 stores
    const float* sc_t = (const float*)(smem + SM_SC);
    const float* sh_t = (const float*)(smem + SM_SH);
    float* outb = out + (size_t)img * 128 * HW;
    const int gh = h0 + row_l;

#pragma unroll
    for (int mt = 0; mt < 4; mt++) {
#pragma unroll
        for (int half = 0; half < 2; half++) {
            int co = wm * 64 + mt * 16 + g + half * 8;
            const float* sk = (co < C1) ? ub + (size_t)co * HW
                                        : vb + (size_t)(co - C1) * HW;
            float scv = sc_t[co], shv = sh_t[co];
#pragma unroll
            for (int nt = 0; nt < 4; nt++) {
                int col = colb + nt * 8 + c4 * 2;
                float2 skv = *(const float2*)(sk + gh * Wn + col);
                float y0 = d[mt][nt][half * 2 + 0] * scv + shv + skv.x;
                float y1 = d[mt][nt][half * 2 + 1] * scv + shv + skv.y;
                *(float2*)(outb + (size_t)co * HW + gh * Wn + col) =
                    make_float2(fmaxf(y0, 0.f), fmaxf(y1, 0.f));
            }
        }
    }
}

extern "C" void kernel_launch(void* const* d_in, const int* in_sizes, int n_in,
                              void* d_out, int out_size) {
    const float* u = (const float*)d_in[0];
    const float* v = (const float*)d_in[1];
    const float* w = (const float*)d_in[2];
    const float* g = (const float*)d_in[3];
    const float* bt = (const float*)d_in[4];
    const float* mn = (const float*)d_in[5];
    const float* vr = (const float*)d_in[6];

    cudaFuncSetAttribute(conv_mma_kernel,
                         cudaFuncAttributeMaxDynamicSharedMemorySize, SM_TOTAL);

    wprep_kernel<<<72, 256>>>(w);
    uprep_kernel<<<UPREP_N / 256, 256>>>(u);
    vprep_kernel<<<VPREP_N / 256, 256>>>(v);
    dim3 grid(64, 32);  // (row pairs, images)
    conv_mma_kernel<<<grid, 512, SM_TOTAL>>>(u, v, g, bt, mn, vr, (float*)d_out);
}